// round 1
// baseline (speedup 1.0000x reference)
#include <cuda_runtime.h>
#include <cstddef>

#define N_NODES 100000
#define N_EDGES 1600000

// Scratch: aggregated messages per node (segment_sum output), 100000*32 floats = 12.8MB
__device__ float g_agg[(size_t)N_NODES * 32];

// ---------------------------------------------------------------------------
// Zero the aggregation buffer. 3.2M floats = 800000 float4 = 3125 blocks x 256.
// ---------------------------------------------------------------------------
__global__ void zero_agg_kernel() {
    int i = blockIdx.x * blockDim.x + threadIdx.x;
    float4 z = make_float4(0.f, 0.f, 0.f, 0.f);
    reinterpret_cast<float4*>(g_agg)[i] = z;
}

// ---------------------------------------------------------------------------
// Edge kernel: per 64-edge tile
//   X[64,96] = [nf[src] | nf[dst] | ef]   (gathered into SMEM)
//   H1 = relu(X @ W1 + b1)   [64,64]
//   H2 = relu(H1 @ W2 + b2)  [64,64]
//   U  = relu(H2 @ W3 + b3)  [64,32]  -> out_ef, atomicAdd into g_agg[dst]
// 256 threads as 16x16 grid; 4x4 (or 4x2) register microtiles.
// SMEM strides padded (100 / 68) so row-distance 4*stride != 0 mod 32 banks.
// ---------------------------------------------------------------------------
__global__ void __launch_bounds__(256, 2)
edge_kernel(const float* __restrict__ nf, const float* __restrict__ ef,
            const int* __restrict__ src, const int* __restrict__ dst,
            const float* __restrict__ W1, const float* __restrict__ b1,
            const float* __restrict__ W2, const float* __restrict__ b2,
            const float* __restrict__ W3, const float* __restrict__ b3,
            float* __restrict__ out_ef)
{
    extern __shared__ float s[];
    float* W1s = s;                  // 96*64 = 6144
    float* W2s = W1s + 6144;         // 64*64 = 4096
    float* W3s = W2s + 4096;         // 64*32 = 2048
    float* b1s = W3s + 2048;         // 64
    float* b2s = b1s + 64;           // 64
    float* b3s = b2s + 64;           // 32
    float* Xs  = b3s + 32;           // 64 rows * stride 100 = 6400
    float* Hs  = Xs + 6400;          // 64 rows * stride 68  = 4352
    // total = 23200 floats = 92800 bytes

    const int tid = threadIdx.x;
    const int e0 = blockIdx.x * 64;

    // ---- stage weights/biases ----
    for (int i = tid * 4; i < 6144; i += 1024)
        *(float4*)(W1s + i) = *(const float4*)(W1 + i);
    for (int i = tid * 4; i < 4096; i += 1024)
        *(float4*)(W2s + i) = *(const float4*)(W2 + i);
    for (int i = tid * 4; i < 2048; i += 1024)
        *(float4*)(W3s + i) = *(const float4*)(W3 + i);
    if (tid < 64)        b1s[tid]       = b1[tid];
    else if (tid < 128)  b2s[tid - 64]  = b2[tid - 64];
    else if (tid < 160)  b3s[tid - 128] = b3[tid - 128];

    // ---- gather X = [nf[src] | nf[dst] | ef] ----
    {
        int g8 = tid >> 3, l8 = tid & 7;    // 32 groups of 8 lanes, each lane one float4
        #pragma unroll
        for (int sg = g8; sg < 128; sg += 32) {       // 64 edges x {src,dst}
            int er = sg >> 1, wh = sg & 1;
            int e = e0 + er;
            int node = wh ? dst[e] : src[e];
            float4 v = *(const float4*)(nf + (size_t)node * 32 + l8 * 4);
            *(float4*)(Xs + er * 100 + wh * 32 + l8 * 4) = v;
        }
        #pragma unroll
        for (int er = g8; er < 64; er += 32) {        // ef rows (contiguous)
            float4 v = *(const float4*)(ef + (size_t)(e0 + er) * 32 + l8 * 4);
            *(float4*)(Xs + er * 100 + 64 + l8 * 4) = v;
        }
    }
    __syncthreads();

    const int tx = tid & 15, ty = tid >> 4;

    // ---- GEMM1: [64,96] x [96,64], 4 rows x 4 cols per thread ----
    {
        float acc[4][4];
        #pragma unroll
        for (int i = 0; i < 4; i++)
            #pragma unroll
            for (int j = 0; j < 4; j++) acc[i][j] = b1s[tx * 4 + j];
        #pragma unroll 4
        for (int k = 0; k < 96; k++) {
            float4 b = *(const float4*)(W1s + k * 64 + tx * 4);
            #pragma unroll
            for (int i = 0; i < 4; i++) {
                float a = Xs[(ty * 4 + i) * 100 + k];
                acc[i][0] += a * b.x; acc[i][1] += a * b.y;
                acc[i][2] += a * b.z; acc[i][3] += a * b.w;
            }
        }
        #pragma unroll
        for (int i = 0; i < 4; i++) {
            float4 v = make_float4(fmaxf(acc[i][0], 0.f), fmaxf(acc[i][1], 0.f),
                                   fmaxf(acc[i][2], 0.f), fmaxf(acc[i][3], 0.f));
            *(float4*)(Hs + (ty * 4 + i) * 68 + tx * 4) = v;
        }
    }
    __syncthreads();

    // ---- GEMM2: [64,64] x [64,64]; write into Xs region (stride 68) ----
    float* H2s = Xs;
    {
        float acc[4][4];
        #pragma unroll
        for (int i = 0; i < 4; i++)
            #pragma unroll
            for (int j = 0; j < 4; j++) acc[i][j] = b2s[tx * 4 + j];
        #pragma unroll 4
        for (int k = 0; k < 64; k++) {
            float4 b = *(const float4*)(W2s + k * 64 + tx * 4);
            #pragma unroll
            for (int i = 0; i < 4; i++) {
                float a = Hs[(ty * 4 + i) * 68 + k];
                acc[i][0] += a * b.x; acc[i][1] += a * b.y;
                acc[i][2] += a * b.z; acc[i][3] += a * b.w;
            }
        }
        __syncthreads();   // all GEMM2 reads of Hs done before... (Hs != Xs, but keep ordering tight)
        #pragma unroll
        for (int i = 0; i < 4; i++) {
            float4 v = make_float4(fmaxf(acc[i][0], 0.f), fmaxf(acc[i][1], 0.f),
                                   fmaxf(acc[i][2], 0.f), fmaxf(acc[i][3], 0.f));
            *(float4*)(H2s + (ty * 4 + i) * 68 + tx * 4) = v;
        }
    }
    __syncthreads();

    // ---- GEMM3: [64,64] x [64,32]; 4 rows x 2 cols per thread ----
    {
        float acc[4][2];
        #pragma unroll
        for (int i = 0; i < 4; i++) {
            acc[i][0] = b3s[tx * 2 + 0];
            acc[i][1] = b3s[tx * 2 + 1];
        }
        #pragma unroll 4
        for (int k = 0; k < 64; k++) {
            float2 b = *(const float2*)(W3s + k * 32 + tx * 2);
            #pragma unroll
            for (int i = 0; i < 4; i++) {
                float a = H2s[(ty * 4 + i) * 68 + k];
                acc[i][0] += a * b.x; acc[i][1] += a * b.y;
            }
        }
        // epilogue: write u_ef + scatter-add into g_agg
        #pragma unroll
        for (int i = 0; i < 4; i++) {
            int e = e0 + ty * 4 + i;
            int d = dst[e];
            float v0 = fmaxf(acc[i][0], 0.f);
            float v1 = fmaxf(acc[i][1], 0.f);
            *(float2*)(out_ef + (size_t)e * 32 + tx * 2) = make_float2(v0, v1);
            atomicAdd(&g_agg[(size_t)d * 32 + tx * 2 + 0], v0);
            atomicAdd(&g_agg[(size_t)d * 32 + tx * 2 + 1], v1);
        }
    }
}

// ---------------------------------------------------------------------------
// Node kernel: per 64-node tile
//   X[64,64] = [nf | agg]
//   three layers as above -> out_nf [64,32]
// ---------------------------------------------------------------------------
__global__ void __launch_bounds__(256, 2)
node_kernel(const float* __restrict__ nf,
            const float* __restrict__ W1, const float* __restrict__ b1,
            const float* __restrict__ W2, const float* __restrict__ b2,
            const float* __restrict__ W3, const float* __restrict__ b3,
            float* __restrict__ out_nf)
{
    extern __shared__ float s[];
    float* W1s = s;                  // 64*64 = 4096
    float* W2s = W1s + 4096;         // 4096
    float* W3s = W2s + 4096;         // 2048
    float* b1s = W3s + 2048;         // 64
    float* b2s = b1s + 64;           // 64
    float* b3s = b2s + 64;           // 32
    float* Xs  = b3s + 32;           // 64 * 68 = 4352
    float* Hs  = Xs + 4352;          // 64 * 68 = 4352
    // total = 19104 floats = 76416 bytes

    const int tid = threadIdx.x;
    const int n0 = blockIdx.x * 64;

    for (int i = tid * 4; i < 4096; i += 1024)
        *(float4*)(W1s + i) = *(const float4*)(W1 + i);
    for (int i = tid * 4; i < 4096; i += 1024)
        *(float4*)(W2s + i) = *(const float4*)(W2 + i);
    for (int i = tid * 4; i < 2048; i += 1024)
        *(float4*)(W3s + i) = *(const float4*)(W3 + i);
    if (tid < 64)        b1s[tid]       = b1[tid];
    else if (tid < 128)  b2s[tid - 64]  = b2[tid - 64];
    else if (tid < 160)  b3s[tid - 128] = b3[tid - 128];

    // gather X = [nf | agg] (zero-fill out-of-range rows)
    for (int i = tid; i < 64 * 16; i += 256) {
        int row = i >> 4, q = i & 15;
        int node = n0 + row;
        float4 v;
        if (node < N_NODES) {
            v = (q < 8) ? *(const float4*)(nf + (size_t)node * 32 + q * 4)
                        : *(const float4*)(g_agg + (size_t)node * 32 + (q - 8) * 4);
        } else {
            v = make_float4(0.f, 0.f, 0.f, 0.f);
        }
        *(float4*)(Xs + row * 68 + q * 4) = v;
    }
    __syncthreads();

    const int tx = tid & 15, ty = tid >> 4;

    // GEMM1: [64,64] x [64,64]
    {
        float acc[4][4];
        #pragma unroll
        for (int i = 0; i < 4; i++)
            #pragma unroll
            for (int j = 0; j < 4; j++) acc[i][j] = b1s[tx * 4 + j];
        #pragma unroll 4
        for (int k = 0; k < 64; k++) {
            float4 b = *(const float4*)(W1s + k * 64 + tx * 4);
            #pragma unroll
            for (int i = 0; i < 4; i++) {
                float a = Xs[(ty * 4 + i) * 68 + k];
                acc[i][0] += a * b.x; acc[i][1] += a * b.y;
                acc[i][2] += a * b.z; acc[i][3] += a * b.w;
            }
        }
        #pragma unroll
        for (int i = 0; i < 4; i++) {
            float4 v = make_float4(fmaxf(acc[i][0], 0.f), fmaxf(acc[i][1], 0.f),
                                   fmaxf(acc[i][2], 0.f), fmaxf(acc[i][3], 0.f));
            *(float4*)(Hs + (ty * 4 + i) * 68 + tx * 4) = v;
        }
    }
    __syncthreads();

    // GEMM2: write back into Xs region
    float* H2s = Xs;
    {
        float acc[4][4];
        #pragma unroll
        for (int i = 0; i < 4; i++)
            #pragma unroll
            for (int j = 0; j < 4; j++) acc[i][j] = b2s[tx * 4 + j];
        #pragma unroll 4
        for (int k = 0; k < 64; k++) {
            float4 b = *(const float4*)(W2s + k * 64 + tx * 4);
            #pragma unroll
            for (int i = 0; i < 4; i++) {
                float a = Hs[(ty * 4 + i) * 68 + k];
                acc[i][0] += a * b.x; acc[i][1] += a * b.y;
                acc[i][2] += a * b.z; acc[i][3] += a * b.w;
            }
        }
        __syncthreads();
        #pragma unroll
        for (int i = 0; i < 4; i++) {
            float4 v = make_float4(fmaxf(acc[i][0], 0.f), fmaxf(acc[i][1], 0.f),
                                   fmaxf(acc[i][2], 0.f), fmaxf(acc[i][3], 0.f));
            *(float4*)(H2s + (ty * 4 + i) * 68 + tx * 4) = v;
        }
    }
    __syncthreads();

    // GEMM3: [64,64] x [64,32]
    {
        float acc[4][2];
        #pragma unroll
        for (int i = 0; i < 4; i++) {
            acc[i][0] = b3s[tx * 2 + 0];
            acc[i][1] = b3s[tx * 2 + 1];
        }
        #pragma unroll 4
        for (int k = 0; k < 64; k++) {
            float2 b = *(const float2*)(W3s + k * 32 + tx * 2);
            #pragma unroll
            for (int i = 0; i < 4; i++) {
                float a = H2s[(ty * 4 + i) * 68 + k];
                acc[i][0] += a * b.x; acc[i][1] += a * b.y;
            }
        }
        #pragma unroll
        for (int i = 0; i < 4; i++) {
            int node = n0 + ty * 4 + i;
            if (node < N_NODES) {
                float v0 = fmaxf(acc[i][0], 0.f);
                float v1 = fmaxf(acc[i][1], 0.f);
                *(float2*)(out_nf + (size_t)node * 32 + tx * 2) = make_float2(v0, v1);
            }
        }
    }
}

// ---------------------------------------------------------------------------
// Launch: zero agg -> edge MLP + scatter -> node MLP. All on default stream,
// graph-capturable (kernel launches only, no allocs).
// Output layout: u_nf [100000*32] followed by u_ef [1600000*32].
// ---------------------------------------------------------------------------
extern "C" void kernel_launch(void* const* d_in, const int* in_sizes, int n_in,
                              void* d_out, int out_size)
{
    const float* nf  = (const float*)d_in[0];
    const float* ef  = (const float*)d_in[1];
    const int*   src = (const int*)d_in[2];
    const int*   dst = (const int*)d_in[3];
    const float* eW1 = (const float*)d_in[4];
    const float* eb1 = (const float*)d_in[5];
    const float* eW2 = (const float*)d_in[6];
    const float* eb2 = (const float*)d_in[7];
    const float* eW3 = (const float*)d_in[8];
    const float* eb3 = (const float*)d_in[9];
    const float* nW1 = (const float*)d_in[10];
    const float* nb1 = (const float*)d_in[11];
    const float* nW2 = (const float*)d_in[12];
    const float* nb2 = (const float*)d_in[13];
    const float* nW3 = (const float*)d_in[14];
    const float* nb3 = (const float*)d_in[15];

    float* out_nf = (float*)d_out;
    float* out_ef = out_nf + (size_t)N_NODES * 32;

    cudaFuncSetAttribute(edge_kernel, cudaFuncAttributeMaxDynamicSharedMemorySize, 92800);
    cudaFuncSetAttribute(node_kernel, cudaFuncAttributeMaxDynamicSharedMemorySize, 76416);

    zero_agg_kernel<<<3125, 256>>>();
    edge_kernel<<<N_EDGES / 64, 256, 92800>>>(nf, ef, src, dst,
                                              eW1, eb1, eW2, eb2, eW3, eb3,
                                              out_ef);
    node_kernel<<<(N_NODES + 63) / 64, 256, 76416>>>(nf,
                                                     nW1, nb1, nW2, nb2, nW3, nb3,
                                                     out_nf);
}

// round 3
// speedup vs baseline: 3.0901x; 3.0901x over previous
#include <cuda_runtime.h>
#include <cuda_bf16.h>
#include <cstdint>
#include <cstddef>

#define N_NODES 100000
#define N_EDGES 1600000
#define EDGE_TILES 10   // 128-edge tiles per CTA -> 1250 CTAs

// ---------------------------------------------------------------------------
// Device scratch
// ---------------------------------------------------------------------------
__device__ float g_agg[(size_t)N_NODES * 32];
__device__ __align__(16) unsigned char g_wimg[100352];

// Weight image layout (bytes), all [N rows][K cols] bf16, padded strides:
//  eW1 hi@0      lo@13312   N=64 S=104 (Kreal 96)
//  eW2 hi@26624  lo@35840   N=64 S=72  (Kreal 64)
//  eW3 hi@45056  lo@49664   N=32 S=72
//  nW1 hi@54272  lo@63488   N=64 S=72
//  nW2 hi@72704  lo@81920   N=64 S=72
//  nW3 hi@91136  lo@95744   N=32 S=72

// ---------------------------------------------------------------------------
// Helpers
// ---------------------------------------------------------------------------
__device__ __forceinline__ uint32_t pack_split(float x0, float x1, uint32_t& lo) {
    __nv_bfloat16 h0 = __float2bfloat16(x0);
    __nv_bfloat16 h1 = __float2bfloat16(x1);
    __nv_bfloat16 l0 = __float2bfloat16(x0 - __bfloat162float(h0));
    __nv_bfloat16 l1 = __float2bfloat16(x1 - __bfloat162float(h1));
    lo = (uint32_t)__bfloat16_as_ushort(l0) | ((uint32_t)__bfloat16_as_ushort(l1) << 16);
    return (uint32_t)__bfloat16_as_ushort(h0) | ((uint32_t)__bfloat16_as_ushort(h1) << 16);
}

__device__ __forceinline__ void mma16816(float c[4], const uint32_t a[4],
                                         uint32_t b0, uint32_t b1) {
    asm volatile(
        "mma.sync.aligned.m16n8k16.row.col.f32.bf16.bf16.f32 "
        "{%0,%1,%2,%3},{%4,%5,%6,%7},{%8,%9},{%0,%1,%2,%3};"
        : "+f"(c[0]), "+f"(c[1]), "+f"(c[2]), "+f"(c[3])
        : "r"(a[0]), "r"(a[1]), "r"(a[2]), "r"(a[3]), "r"(b0), "r"(b1));
}

__device__ __forceinline__ void red4(float* p, float4 v) {
    asm volatile("red.global.add.v4.f32 [%0], {%1,%2,%3,%4};"
                 :: "l"(p), "f"(v.x), "f"(v.y), "f"(v.z), "f"(v.w) : "memory");
}

// 3-product split mma: c += Ah*Bh + Ah*Bl + Al*Bh
__device__ __forceinline__ void mma3(float c[4], const uint32_t ah[4], const uint32_t al[4],
                                     const __nv_bfloat16* ph, const __nv_bfloat16* pl) {
    uint32_t bh0 = *(const uint32_t*)ph, bh1 = *(const uint32_t*)(ph + 8);
    uint32_t bl0 = *(const uint32_t*)pl, bl1 = *(const uint32_t*)(pl + 8);
    mma16816(c, ah, bh0, bh1);
    mma16816(c, ah, bl0, bl1);
    mma16816(c, al, bh0, bh1);
}

// bias + relu + split c[8][4] (N=64) -> next-layer A fragments (4 k-tiles)
__device__ __forceinline__ void convert(const float c[8][4], const float* bias, int cc,
                                        uint32_t ah[4][4], uint32_t al[4][4]) {
    #pragma unroll
    for (int kk = 0; kk < 4; kk++) {
        #pragma unroll
        for (int h = 0; h < 2; h++) {
            int j = 2 * kk + h;
            float2 bb = *(const float2*)(bias + 8 * j + 2 * cc);
            float x0 = fmaxf(c[j][0] + bb.x, 0.f);
            float x1 = fmaxf(c[j][1] + bb.y, 0.f);
            float x2 = fmaxf(c[j][2] + bb.x, 0.f);
            float x3 = fmaxf(c[j][3] + bb.y, 0.f);
            ah[kk][2 * h]     = pack_split(x0, x1, al[kk][2 * h]);
            ah[kk][2 * h + 1] = pack_split(x2, x3, al[kk][2 * h + 1]);
        }
    }
}

// ---------------------------------------------------------------------------
// Prep: transpose + bf16 hi/lo split into g_wimg ([N][S] per matrix)
// ---------------------------------------------------------------------------
__global__ void prep_weights(const float* __restrict__ eW1, const float* __restrict__ eW2,
                             const float* __restrict__ eW3, const float* __restrict__ nW1,
                             const float* __restrict__ nW2, const float* __restrict__ nW3) {
    int idx = blockIdx.x * blockDim.x + threadIdx.x;   // 0..25087
    const float* W; int N, Kreal, S; size_t off; int local;
    if      (idx <  6656) { W = eW1; N = 64; Kreal = 96; S = 104; off = 0;     local = idx; }
    else if (idx < 11264) { W = eW2; N = 64; Kreal = 64; S = 72;  off = 26624; local = idx - 6656; }
    else if (idx < 13568) { W = eW3; N = 32; Kreal = 64; S = 72;  off = 45056; local = idx - 11264; }
    else if (idx < 18176) { W = nW1; N = 64; Kreal = 64; S = 72;  off = 54272; local = idx - 13568; }
    else if (idx < 22784) { W = nW2; N = 64; Kreal = 64; S = 72;  off = 72704; local = idx - 18176; }
    else                  { W = nW3; N = 32; Kreal = 64; S = 72;  off = 91136; local = idx - 22784; }
    size_t img = (size_t)N * S * 2;
    int n = local / S, k = local % S;
    float val = (k < Kreal) ? W[(size_t)k * N + n] : 0.f;
    __nv_bfloat16 h = __float2bfloat16(val);
    __nv_bfloat16 l = __float2bfloat16(val - __bfloat162float(h));
    *(unsigned short*)(g_wimg + off + ((size_t)n * S + k) * 2)       = __bfloat16_as_ushort(h);
    *(unsigned short*)(g_wimg + off + img + ((size_t)n * S + k) * 2) = __bfloat16_as_ushort(l);
}

__global__ void zero_agg_kernel() {
    int i = blockIdx.x * blockDim.x + threadIdx.x;
    reinterpret_cast<float4*>(g_agg)[i] = make_float4(0.f, 0.f, 0.f, 0.f);
}

// ---------------------------------------------------------------------------
// Edge kernel: 256 threads = 8 warps, each warp = 16 edges per tile, 10 tiles.
// Whole MLP register-resident per warp via mma.sync fragment chaining.
// ---------------------------------------------------------------------------
#define EDGE_WB   54272
#define EDGE_SMEM (54912 + 8 * 2304)   // weights+bias + 8 warp bufs (16x36 f32)

__global__ void __launch_bounds__(256, 2)
edge_kernel(const float* __restrict__ nf, const float* __restrict__ ef,
            const int* __restrict__ src, const int* __restrict__ dst,
            const float* __restrict__ b1, const float* __restrict__ b2,
            const float* __restrict__ b3, float* __restrict__ out_ef) {
    extern __shared__ char sm[];
    const int tid = threadIdx.x, wid = tid >> 5, lane = tid & 31;

    {   // stage weight images (already laid out)
        const uint4* g = (const uint4*)g_wimg;
        uint4* d4 = (uint4*)sm;
        for (int i = tid; i < EDGE_WB / 16; i += 256) d4[i] = g[i];
    }
    float* bias = (float*)(sm + EDGE_WB);
    if (tid < 64)       bias[tid] = b1[tid];
    else if (tid < 128) bias[tid] = b2[tid - 64];
    else if (tid < 160) bias[tid] = b3[tid - 128];
    float* buf = (float*)(sm + 54912) + wid * 576;   // 16 x 36 floats
    __syncthreads();

    const int r = lane >> 2, cc = lane & 3;
    const __nv_bfloat16* W1h = (const __nv_bfloat16*)(sm);
    const __nv_bfloat16* W1l = (const __nv_bfloat16*)(sm + 13312);
    const __nv_bfloat16* W2h = (const __nv_bfloat16*)(sm + 26624);
    const __nv_bfloat16* W2l = (const __nv_bfloat16*)(sm + 35840);
    const __nv_bfloat16* W3h = (const __nv_bfloat16*)(sm + 45056);
    const __nv_bfloat16* W3l = (const __nv_bfloat16*)(sm + 49664);

    for (int t = 0; t < EDGE_TILES; t++) {
        const int e0w = (blockIdx.x * EDGE_TILES + t) * 128 + wid * 16;
        const int ra = e0w + r, rb = ra + 8;
        const int sa = src[ra], sb = src[rb], da = dst[ra], db = dst[rb];
        const float* PA[3] = { nf + (size_t)sa * 32, nf + (size_t)da * 32, ef + (size_t)ra * 32 };
        const float* PB[3] = { nf + (size_t)sb * 32, nf + (size_t)db * 32, ef + (size_t)rb * 32 };

        float c[8][4];
        #pragma unroll
        for (int j = 0; j < 8; j++) { c[j][0] = c[j][1] = c[j][2] = c[j][3] = 0.f; }

        // ---- L1: K = 96, gather A fragments straight from global ----
        #pragma unroll
        for (int kt = 0; kt < 6; kt++) {
            const float* pa = PA[kt >> 1];
            const float* pb = PB[kt >> 1];
            const int o = ((kt & 1) << 4) + 2 * cc;
            float2 va0 = *(const float2*)(pa + o), va1 = *(const float2*)(pa + o + 8);
            float2 vb0 = *(const float2*)(pb + o), vb1 = *(const float2*)(pb + o + 8);
            uint32_t ah[4], al[4];
            ah[0] = pack_split(va0.x, va0.y, al[0]);
            ah[1] = pack_split(vb0.x, vb0.y, al[1]);
            ah[2] = pack_split(va1.x, va1.y, al[2]);
            ah[3] = pack_split(vb1.x, vb1.y, al[3]);
            const int kb = kt * 16 + 2 * cc;
            #pragma unroll
            for (int j = 0; j < 8; j++)
                mma3(c[j], ah, al, W1h + (8 * j + r) * 104 + kb, W1l + (8 * j + r) * 104 + kb);
        }

        uint32_t a2h[4][4], a2l[4][4];
        convert(c, bias, cc, a2h, a2l);

        // ---- L2: K = 64 ----
        #pragma unroll
        for (int j = 0; j < 8; j++) { c[j][0] = c[j][1] = c[j][2] = c[j][3] = 0.f; }
        #pragma unroll
        for (int kt = 0; kt < 4; kt++) {
            const int kb = kt * 16 + 2 * cc;
            #pragma unroll
            for (int j = 0; j < 8; j++)
                mma3(c[j], a2h[kt], a2l[kt], W2h + (8 * j + r) * 72 + kb, W2l + (8 * j + r) * 72 + kb);
        }

        uint32_t a3h[4][4], a3l[4][4];
        convert(c, bias + 64, cc, a3h, a3l);

        // ---- L3: K = 64, N = 32 ----
        float c3[4][4];
        #pragma unroll
        for (int j = 0; j < 4; j++) { c3[j][0] = c3[j][1] = c3[j][2] = c3[j][3] = 0.f; }
        #pragma unroll
        for (int kt = 0; kt < 4; kt++) {
            const int kb = kt * 16 + 2 * cc;
            #pragma unroll
            for (int j = 0; j < 4; j++)
                mma3(c3[j], a3h[kt], a3l[kt], W3h + (8 * j + r) * 72 + kb, W3l + (8 * j + r) * 72 + kb);
        }

        // ---- epilogue: transpose via warp buf, coalesced store + vector RED ----
        #pragma unroll
        for (int j = 0; j < 4; j++) {
            float2 bb = *(const float2*)(bias + 128 + 8 * j + 2 * cc);
            int col = 8 * j + 2 * cc;
            buf[r * 36 + col]            = fmaxf(c3[j][0] + bb.x, 0.f);
            buf[r * 36 + col + 1]        = fmaxf(c3[j][1] + bb.y, 0.f);
            buf[(r + 8) * 36 + col]      = fmaxf(c3[j][2] + bb.x, 0.f);
            buf[(r + 8) * 36 + col + 1]  = fmaxf(c3[j][3] + bb.y, 0.f);
        }
        __syncwarp();
        {
            const int row = lane >> 1, half = lane & 1;
            const int e_row = e0w + row;
            const int d = dst[e_row];
            const float* bp = buf + row * 36 + half * 16;
            float4 v0 = *(const float4*)(bp);
            float4 v1 = *(const float4*)(bp + 4);
            float4 v2 = *(const float4*)(bp + 8);
            float4 v3 = *(const float4*)(bp + 12);
            float4* op = (float4*)(out_ef + (size_t)e_row * 32 + half * 16);
            op[0] = v0; op[1] = v1; op[2] = v2; op[3] = v3;
            float* ap = g_agg + (size_t)d * 32 + half * 16;
            red4(ap, v0); red4(ap + 4, v1); red4(ap + 8, v2); red4(ap + 12, v3);
        }
        __syncwarp();
    }
}

// ---------------------------------------------------------------------------
// Node kernel: 256 threads = 8 warps x 16 nodes. Same register chaining.
// ---------------------------------------------------------------------------
#define NODE_WB   46080
#define NODE_SMEM (46720 + 8 * 2304)

__global__ void __launch_bounds__(256, 2)
node_kernel(const float* __restrict__ nf,
            const float* __restrict__ b1, const float* __restrict__ b2,
            const float* __restrict__ b3, float* __restrict__ out_nf) {
    extern __shared__ char sm[];
    const int tid = threadIdx.x, wid = tid >> 5, lane = tid & 31;

    {
        const uint4* g = (const uint4*)(g_wimg + EDGE_WB);
        uint4* d4 = (uint4*)sm;
        for (int i = tid; i < NODE_WB / 16; i += 256) d4[i] = g[i];
    }
    float* bias = (float*)(sm + NODE_WB);
    if (tid < 64)       bias[tid] = b1[tid];
    else if (tid < 128) bias[tid] = b2[tid - 64];
    else if (tid < 160) bias[tid] = b3[tid - 128];
    float* buf = (float*)(sm + 46720) + wid * 576;
    __syncthreads();

    const int r = lane >> 2, cc = lane & 3;
    const __nv_bfloat16* W1h = (const __nv_bfloat16*)(sm);
    const __nv_bfloat16* W1l = (const __nv_bfloat16*)(sm + 9216);
    const __nv_bfloat16* W2h = (const __nv_bfloat16*)(sm + 18432);
    const __nv_bfloat16* W2l = (const __nv_bfloat16*)(sm + 27648);
    const __nv_bfloat16* W3h = (const __nv_bfloat16*)(sm + 36864);
    const __nv_bfloat16* W3l = (const __nv_bfloat16*)(sm + 41472);

    const int n0w = blockIdx.x * 128 + wid * 16;
    const int ra = min(n0w + r, N_NODES - 1);
    const int rb = min(n0w + r + 8, N_NODES - 1);
    const float* PA[2] = { nf + (size_t)ra * 32, g_agg + (size_t)ra * 32 };
    const float* PB[2] = { nf + (size_t)rb * 32, g_agg + (size_t)rb * 32 };

    float c[8][4];
    #pragma unroll
    for (int j = 0; j < 8; j++) { c[j][0] = c[j][1] = c[j][2] = c[j][3] = 0.f; }

    // ---- L1: K = 64 ([nf | agg]) ----
    #pragma unroll
    for (int kt = 0; kt < 4; kt++) {
        const float* pa = PA[kt >> 1];
        const float* pb = PB[kt >> 1];
        const int o = ((kt & 1) << 4) + 2 * cc;
        float2 va0 = *(const float2*)(pa + o), va1 = *(const float2*)(pa + o + 8);
        float2 vb0 = *(const float2*)(pb + o), vb1 = *(const float2*)(pb + o + 8);
        uint32_t ah[4], al[4];
        ah[0] = pack_split(va0.x, va0.y, al[0]);
        ah[1] = pack_split(vb0.x, vb0.y, al[1]);
        ah[2] = pack_split(va1.x, va1.y, al[2]);
        ah[3] = pack_split(vb1.x, vb1.y, al[3]);
        const int kb = kt * 16 + 2 * cc;
        #pragma unroll
        for (int j = 0; j < 8; j++)
            mma3(c[j], ah, al, W1h + (8 * j + r) * 72 + kb, W1l + (8 * j + r) * 72 + kb);
    }

    uint32_t a2h[4][4], a2l[4][4];
    convert(c, bias, cc, a2h, a2l);

    // ---- L2 ----
    #pragma unroll
    for (int j = 0; j < 8; j++) { c[j][0] = c[j][1] = c[j][2] = c[j][3] = 0.f; }
    #pragma unroll
    for (int kt = 0; kt < 4; kt++) {
        const int kb = kt * 16 + 2 * cc;
        #pragma unroll
        for (int j = 0; j < 8; j++)
            mma3(c[j], a2h[kt], a2l[kt], W2h + (8 * j + r) * 72 + kb, W2l + (8 * j + r) * 72 + kb);
    }

    uint32_t a3h[4][4], a3l[4][4];
    convert(c, bias + 64, cc, a3h, a3l);

    // ---- L3: N = 32 ----
    float c3[4][4];
    #pragma unroll
    for (int j = 0; j < 4; j++) { c3[j][0] = c3[j][1] = c3[j][2] = c3[j][3] = 0.f; }
    #pragma unroll
    for (int kt = 0; kt < 4; kt++) {
        const int kb = kt * 16 + 2 * cc;
        #pragma unroll
        for (int j = 0; j < 4; j++)
            mma3(c3[j], a3h[kt], a3l[kt], W3h + (8 * j + r) * 72 + kb, W3l + (8 * j + r) * 72 + kb);
    }

    #pragma unroll
    for (int j = 0; j < 4; j++) {
        float2 bb = *(const float2*)(bias + 128 + 8 * j + 2 * cc);
        int col = 8 * j + 2 * cc;
        buf[r * 36 + col]           = fmaxf(c3[j][0] + bb.x, 0.f);
        buf[r * 36 + col + 1]       = fmaxf(c3[j][1] + bb.y, 0.f);
        buf[(r + 8) * 36 + col]     = fmaxf(c3[j][2] + bb.x, 0.f);
        buf[(r + 8) * 36 + col + 1] = fmaxf(c3[j][3] + bb.y, 0.f);
    }
    __syncwarp();
    {
        const int row = lane >> 1, half = lane & 1;
        const int n_row = n0w + row;
        if (n_row < N_NODES) {
            const float* bp = buf + row * 36 + half * 16;
            float4* op = (float4*)(out_nf + (size_t)n_row * 32 + half * 16);
            op[0] = *(const float4*)(bp);
            op[1] = *(const float4*)(bp + 4);
            op[2] = *(const float4*)(bp + 8);
            op[3] = *(const float4*)(bp + 12);
        }
    }
}

// ---------------------------------------------------------------------------
extern "C" void kernel_launch(void* const* d_in, const int* in_sizes, int n_in,
                              void* d_out, int out_size) {
    const float* nf  = (const float*)d_in[0];
    const float* ef  = (const float*)d_in[1];
    const int*   src = (const int*)d_in[2];
    const int*   dst = (const int*)d_in[3];
    const float* eW1 = (const float*)d_in[4];
    const float* eb1 = (const float*)d_in[5];
    const float* eW2 = (const float*)d_in[6];
    const float* eb2 = (const float*)d_in[7];
    const float* eW3 = (const float*)d_in[8];
    const float* eb3 = (const float*)d_in[9];
    const float* nW1 = (const float*)d_in[10];
    const float* nb1 = (const float*)d_in[11];
    const float* nW2 = (const float*)d_in[12];
    const float* nb2 = (const float*)d_in[13];
    const float* nW3 = (const float*)d_in[14];
    const float* nb3 = (const float*)d_in[15];

    float* out_nf = (float*)d_out;
    float* out_ef = out_nf + (size_t)N_NODES * 32;

    cudaFuncSetAttribute(edge_kernel, cudaFuncAttributeMaxDynamicSharedMemorySize, EDGE_SMEM);
    cudaFuncSetAttribute(node_kernel, cudaFuncAttributeMaxDynamicSharedMemorySize, NODE_SMEM);

    prep_weights<<<196, 128>>>(eW1, eW2, eW3, nW1, nW2, nW3);
    zero_agg_kernel<<<3125, 256>>>();
    edge_kernel<<<N_EDGES / (128 * EDGE_TILES), 256, EDGE_SMEM>>>(
        nf, ef, src, dst, eb1, eb2, eb3, out_ef);
    node_kernel<<<(N_NODES + 127) / 128, 256, NODE_SMEM>>>(
        nf, nb1, nb2, nb3, out_nf);
}

// round 4
// speedup vs baseline: 3.5386x; 1.1451x over previous
#include <cuda_runtime.h>
#include <cuda_bf16.h>
#include <cstdint>
#include <cstddef>

#define N_NODES 100000
#define N_EDGES 1600000
#define EDGE_TILES 10   // 128-edge tiles per CTA -> 1250 CTAs
#define NODE_TILES 2    // 128-node tiles per CTA -> 391 CTAs

// ---------------------------------------------------------------------------
// Device scratch
// ---------------------------------------------------------------------------
__device__ float g_agg[(size_t)N_NODES * 32];
// Fragment-order weight images: per (mat, kt, j, lane) a uint4 {bh0,bh1,bl0,bl1}
// eW1: uint4[   0..1535]  (6 kt x 8 j x 32 lanes)
// eW2: uint4[1536..2559]  (4 x 8 x 32)
// eW3: uint4[2560..3071]  (4 x 4 x 32)
// nW1: uint4[3072..4095]
// nW2: uint4[4096..5119]
// nW3: uint4[5120..5631]
__device__ __align__(16) uint4 g_wfrag[5632];

// ---------------------------------------------------------------------------
// Helpers
// ---------------------------------------------------------------------------
__device__ __forceinline__ uint32_t split2(float x0, float x1, uint32_t& lo) {
    uint32_t hw;
    asm("cvt.rn.bf16x2.f32 %0, %1, %2;" : "=r"(hw) : "f"(x1), "f"(x0));
    float h0 = __uint_as_float(hw << 16);
    float h1 = __uint_as_float(hw & 0xffff0000u);
    asm("cvt.rn.bf16x2.f32 %0, %1, %2;" : "=r"(lo) : "f"(x1 - h1), "f"(x0 - h0));
    return hw;
}

__device__ __forceinline__ void mma16816(float c[4], const uint32_t a[4],
                                         uint32_t b0, uint32_t b1) {
    asm volatile(
        "mma.sync.aligned.m16n8k16.row.col.f32.bf16.bf16.f32 "
        "{%0,%1,%2,%3},{%4,%5,%6,%7},{%8,%9},{%0,%1,%2,%3};"
        : "+f"(c[0]), "+f"(c[1]), "+f"(c[2]), "+f"(c[3])
        : "r"(a[0]), "r"(a[1]), "r"(a[2]), "r"(a[3]), "r"(b0), "r"(b1));
}

// c += Ah*Bh + Ah*Bl + Al*Bh  with one LDS.128 for the whole B fragment
__device__ __forceinline__ void mma3f(float c[4], const uint32_t ah[4], const uint32_t al[4],
                                      const uint4* f) {
    uint4 b = *f;
    mma16816(c, ah, b.x, b.y);
    mma16816(c, ah, b.z, b.w);
    mma16816(c, al, b.x, b.y);
}

__device__ __forceinline__ void red4(float* p, float4 v) {
    asm volatile("red.global.add.v4.f32 [%0], {%1,%2,%3,%4};"
                 :: "l"(p), "f"(v.x), "f"(v.y), "f"(v.z), "f"(v.w) : "memory");
}

// bias + relu + split c[8][4] (N=64) -> next-layer A fragments (4 k-tiles)
__device__ __forceinline__ void convert(const float c[8][4], const float* bias, int cc,
                                        uint32_t ah[4][4], uint32_t al[4][4]) {
    #pragma unroll
    for (int kk = 0; kk < 4; kk++) {
        #pragma unroll
        for (int h = 0; h < 2; h++) {
            int j = 2 * kk + h;
            float2 bb = *(const float2*)(bias + 8 * j + 2 * cc);
            float x0 = fmaxf(c[j][0] + bb.x, 0.f);
            float x1 = fmaxf(c[j][1] + bb.y, 0.f);
            float x2 = fmaxf(c[j][2] + bb.x, 0.f);
            float x3 = fmaxf(c[j][3] + bb.y, 0.f);
            ah[kk][2 * h]     = split2(x0, x1, al[kk][2 * h]);
            ah[kk][2 * h + 1] = split2(x2, x3, al[kk][2 * h + 1]);
        }
    }
}

// ---------------------------------------------------------------------------
// Prep: build fragment-order hi/lo bf16 weight images. One uint4 per thread.
// Fragment (mat, kt, j, lane): n = 8*j + (lane>>2), k0 = kt*16 + 2*(lane&3)
//   words = { pack(W[k0][n],W[k0+1][n]) hi, pack(W[k0+8][n],W[k0+9][n]) hi,
//             same lo, same lo }
// ---------------------------------------------------------------------------
__global__ void prep_weights(const float* __restrict__ eW1, const float* __restrict__ eW2,
                             const float* __restrict__ eW3, const float* __restrict__ nW1,
                             const float* __restrict__ nW2, const float* __restrict__ nW3) {
    int id = blockIdx.x * blockDim.x + threadIdx.x;
    if (id >= 5632) return;
    const float* W; int NJ, N; int rel;
    if      (id < 1536) { W = eW1; NJ = 8; N = 64; rel = id; }
    else if (id < 2560) { W = eW2; NJ = 8; N = 64; rel = id - 1536; }
    else if (id < 3072) { W = eW3; NJ = 4; N = 32; rel = id - 2560; }
    else if (id < 4096) { W = nW1; NJ = 8; N = 64; rel = id - 3072; }
    else if (id < 5120) { W = nW2; NJ = 8; N = 64; rel = id - 4096; }
    else                { W = nW3; NJ = 4; N = 32; rel = id - 5120; }
    int lane = rel & 31, fi = rel >> 5;
    int kt = fi / NJ, j = fi % NJ;
    int n = 8 * j + (lane >> 2);
    int k0 = kt * 16 + 2 * (lane & 3);
    float x0 = W[(size_t)k0 * N + n];
    float x1 = W[(size_t)(k0 + 1) * N + n];
    float x2 = W[(size_t)(k0 + 8) * N + n];
    float x3 = W[(size_t)(k0 + 9) * N + n];
    uint4 o;
    o.x = split2(x0, x1, o.z);
    o.y = split2(x2, x3, o.w);
    g_wfrag[id] = o;
}

__global__ void zero_agg_kernel() {
    int i = blockIdx.x * blockDim.x + threadIdx.x;
    reinterpret_cast<float4*>(g_agg)[i] = make_float4(0.f, 0.f, 0.f, 0.f);
}

// ---------------------------------------------------------------------------
// Edge kernel: 256 threads = 8 warps, each warp = 16 edges/tile, 10 tiles.
// Register-resident split-bf16 MLP via mma.sync fragment chaining.
// SMEM: 3072 uint4 weight frags (49152 B) + 160 bias floats + 8 warp bufs.
// ---------------------------------------------------------------------------
#define EDGE_WU4  3072
#define EDGE_SMEM (49152 + 640 + 8 * 2304)

__global__ void __launch_bounds__(256, 2)
edge_kernel(const float* __restrict__ nf, const float* __restrict__ ef,
            const int* __restrict__ src, const int* __restrict__ dst,
            const float* __restrict__ b1, const float* __restrict__ b2,
            const float* __restrict__ b3, float* __restrict__ out_ef) {
    extern __shared__ char sm[];
    const int tid = threadIdx.x, wid = tid >> 5, lane = tid & 31;

    uint4* wf = (uint4*)sm;
    for (int i = tid; i < EDGE_WU4; i += 256) wf[i] = g_wfrag[i];
    float* bias = (float*)(sm + 49152);
    if (tid < 64)       bias[tid] = b1[tid];
    else if (tid < 128) bias[tid] = b2[tid - 64];
    else if (tid < 160) bias[tid] = b3[tid - 128];
    float* buf = (float*)(sm + 49792) + wid * 576;
    __syncthreads();

    const int r = lane >> 2, cc = lane & 3;
    const uint4* F1 = wf;                  // 6 kt x 8 j
    const uint4* F2 = wf + 1536;           // 4 x 8
    const uint4* F3 = wf + 2560;           // 4 x 4

    for (int t = 0; t < EDGE_TILES; t++) {
        const int e0w = (blockIdx.x * EDGE_TILES + t) * 128 + wid * 16;
        const int ra = e0w + r, rb = ra + 8;
        const int sa = src[ra], sb = src[rb], da = dst[ra], db = dst[rb];
        const float* PA[3] = { nf + (size_t)sa * 32, nf + (size_t)da * 32, ef + (size_t)ra * 32 };
        const float* PB[3] = { nf + (size_t)sb * 32, nf + (size_t)db * 32, ef + (size_t)rb * 32 };

        float c[8][4];
        #pragma unroll
        for (int j = 0; j < 8; j++) { c[j][0] = c[j][1] = c[j][2] = c[j][3] = 0.f; }

        // ---- L1: K = 96, A fragments straight from global ----
        #pragma unroll
        for (int kt = 0; kt < 6; kt++) {
            const float* pa = PA[kt >> 1];
            const float* pb = PB[kt >> 1];
            const int o = ((kt & 1) << 4) + 2 * cc;
            float2 va0 = *(const float2*)(pa + o), va1 = *(const float2*)(pa + o + 8);
            float2 vb0 = *(const float2*)(pb + o), vb1 = *(const float2*)(pb + o + 8);
            uint32_t ah[4], al[4];
            ah[0] = split2(va0.x, va0.y, al[0]);
            ah[1] = split2(vb0.x, vb0.y, al[1]);
            ah[2] = split2(va1.x, va1.y, al[2]);
            ah[3] = split2(vb1.x, vb1.y, al[3]);
            const uint4* fp = F1 + kt * 256 + lane;
            #pragma unroll
            for (int j = 0; j < 8; j++)
                mma3f(c[j], ah, al, fp + j * 32);
        }

        uint32_t a2h[4][4], a2l[4][4];
        convert(c, bias, cc, a2h, a2l);

        // ---- L2: K = 64 ----
        #pragma unroll
        for (int j = 0; j < 8; j++) { c[j][0] = c[j][1] = c[j][2] = c[j][3] = 0.f; }
        #pragma unroll
        for (int kt = 0; kt < 4; kt++) {
            const uint4* fp = F2 + kt * 256 + lane;
            #pragma unroll
            for (int j = 0; j < 8; j++)
                mma3f(c[j], a2h[kt], a2l[kt], fp + j * 32);
        }

        uint32_t a3h[4][4], a3l[4][4];
        convert(c, bias + 64, cc, a3h, a3l);

        // ---- L3: K = 64, N = 32 ----
        float c3[4][4];
        #pragma unroll
        for (int j = 0; j < 4; j++) { c3[j][0] = c3[j][1] = c3[j][2] = c3[j][3] = 0.f; }
        #pragma unroll
        for (int kt = 0; kt < 4; kt++) {
            const uint4* fp = F3 + kt * 128 + lane;
            #pragma unroll
            for (int j = 0; j < 4; j++)
                mma3f(c3[j], a3h[kt], a3l[kt], fp + j * 32);
        }

        // ---- epilogue: transpose via warp buf -> coalesced store + vector RED ----
        #pragma unroll
        for (int j = 0; j < 4; j++) {
            float2 bb = *(const float2*)(bias + 128 + 8 * j + 2 * cc);
            int col = 8 * j + 2 * cc;
            buf[r * 36 + col]            = fmaxf(c3[j][0] + bb.x, 0.f);
            buf[r * 36 + col + 1]        = fmaxf(c3[j][1] + bb.y, 0.f);
            buf[(r + 8) * 36 + col]      = fmaxf(c3[j][2] + bb.x, 0.f);
            buf[(r + 8) * 36 + col + 1]  = fmaxf(c3[j][3] + bb.y, 0.f);
        }
        __syncwarp();
        {
            const int row = lane >> 1, half = lane & 1;
            const int e_row = e0w + row;
            const int d = dst[e_row];
            const float* bp = buf + row * 36 + half * 16;
            float4 v0 = *(const float4*)(bp);
            float4 v1 = *(const float4*)(bp + 4);
            float4 v2 = *(const float4*)(bp + 8);
            float4 v3 = *(const float4*)(bp + 12);
            float4* op = (float4*)(out_ef + (size_t)e_row * 32 + half * 16);
            op[0] = v0; op[1] = v1; op[2] = v2; op[3] = v3;
            float* ap = g_agg + (size_t)d * 32 + half * 16;
            red4(ap, v0); red4(ap + 4, v1); red4(ap + 8, v2); red4(ap + 12, v3);
        }
        __syncwarp();
    }
}

// ---------------------------------------------------------------------------
// Node kernel: 256 threads, NODE_TILES x 128 nodes per CTA.
// ---------------------------------------------------------------------------
#define NODE_WU4  2560
#define NODE_SMEM (40960 + 640 + 8 * 2304)

__global__ void __launch_bounds__(256, 2)
node_kernel(const float* __restrict__ nf,
            const float* __restrict__ b1, const float* __restrict__ b2,
            const float* __restrict__ b3, float* __restrict__ out_nf) {
    extern __shared__ char sm[];
    const int tid = threadIdx.x, wid = tid >> 5, lane = tid & 31;

    uint4* wf = (uint4*)sm;
    for (int i = tid; i < NODE_WU4; i += 256) wf[i] = g_wfrag[3072 + i];
    float* bias = (float*)(sm + 40960);
    if (tid < 64)       bias[tid] = b1[tid];
    else if (tid < 128) bias[tid] = b2[tid - 64];
    else if (tid < 160) bias[tid] = b3[tid - 128];
    float* buf = (float*)(sm + 41600) + wid * 576;
    __syncthreads();

    const int r = lane >> 2, cc = lane & 3;
    const uint4* F1 = wf;                  // 4 kt x 8 j
    const uint4* F2 = wf + 1024;
    const uint4* F3 = wf + 2048;           // 4 x 4

    for (int t = 0; t < NODE_TILES; t++) {
        const int n0w = (blockIdx.x * NODE_TILES + t) * 128 + wid * 16;
        if (n0w >= N_NODES) break;
        const int ra = min(n0w + r, N_NODES - 1);
        const int rb = min(n0w + r + 8, N_NODES - 1);
        const float* PA[2] = { nf + (size_t)ra * 32, g_agg + (size_t)ra * 32 };
        const float* PB[2] = { nf + (size_t)rb * 32, g_agg + (size_t)rb * 32 };

        float c[8][4];
        #pragma unroll
        for (int j = 0; j < 8; j++) { c[j][0] = c[j][1] = c[j][2] = c[j][3] = 0.f; }

        // ---- L1: K = 64 ([nf | agg]) ----
        #pragma unroll
        for (int kt = 0; kt < 4; kt++) {
            const float* pa = PA[kt >> 1];
            const float* pb = PB[kt >> 1];
            const int o = ((kt & 1) << 4) + 2 * cc;
            float2 va0 = *(const float2*)(pa + o), va1 = *(const float2*)(pa + o + 8);
            float2 vb0 = *(const float2*)(pb + o), vb1 = *(const float2*)(pb + o + 8);
            uint32_t ah[4], al[4];
            ah[0] = split2(va0.x, va0.y, al[0]);
            ah[1] = split2(vb0.x, vb0.y, al[1]);
            ah[2] = split2(va1.x, va1.y, al[2]);
            ah[3] = split2(vb1.x, vb1.y, al[3]);
            const uint4* fp = F1 + kt * 256 + lane;
            #pragma unroll
            for (int j = 0; j < 8; j++)
                mma3f(c[j], ah, al, fp + j * 32);
        }

        uint32_t a2h[4][4], a2l[4][4];
        convert(c, bias, cc, a2h, a2l);

        #pragma unroll
        for (int j = 0; j < 8; j++) { c[j][0] = c[j][1] = c[j][2] = c[j][3] = 0.f; }
        #pragma unroll
        for (int kt = 0; kt < 4; kt++) {
            const uint4* fp = F2 + kt * 256 + lane;
            #pragma unroll
            for (int j = 0; j < 8; j++)
                mma3f(c[j], a2h[kt], a2l[kt], fp + j * 32);
        }

        uint32_t a3h[4][4], a3l[4][4];
        convert(c, bias + 64, cc, a3h, a3l);

        float c3[4][4];
        #pragma unroll
        for (int j = 0; j < 4; j++) { c3[j][0] = c3[j][1] = c3[j][2] = c3[j][3] = 0.f; }
        #pragma unroll
        for (int kt = 0; kt < 4; kt++) {
            const uint4* fp = F3 + kt * 128 + lane;
            #pragma unroll
            for (int j = 0; j < 4; j++)
                mma3f(c3[j], a3h[kt], a3l[kt], fp + j * 32);
        }

        #pragma unroll
        for (int j = 0; j < 4; j++) {
            float2 bb = *(const float2*)(bias + 128 + 8 * j + 2 * cc);
            int col = 8 * j + 2 * cc;
            buf[r * 36 + col]           = fmaxf(c3[j][0] + bb.x, 0.f);
            buf[r * 36 + col + 1]       = fmaxf(c3[j][1] + bb.y, 0.f);
            buf[(r + 8) * 36 + col]     = fmaxf(c3[j][2] + bb.x, 0.f);
            buf[(r + 8) * 36 + col + 1] = fmaxf(c3[j][3] + bb.y, 0.f);
        }
        __syncwarp();
        {
            const int row = lane >> 1, half = lane & 1;
            const int n_row = n0w + row;
            if (n_row < N_NODES) {
                const float* bp = buf + row * 36 + half * 16;
                float4* op = (float4*)(out_nf + (size_t)n_row * 32 + half * 16);
                op[0] = *(const float4*)(bp);
                op[1] = *(const float4*)(bp + 4);
                op[2] = *(const float4*)(bp + 8);
                op[3] = *(const float4*)(bp + 12);
            }
        }
        __syncwarp();
    }
}

// ---------------------------------------------------------------------------
extern "C" void kernel_launch(void* const* d_in, const int* in_sizes, int n_in,
                              void* d_out, int out_size) {
    const float* nf  = (const float*)d_in[0];
    const float* ef  = (const float*)d_in[1];
    const int*   src = (const int*)d_in[2];
    const int*   dst = (const int*)d_in[3];
    const float* eW1 = (const float*)d_in[4];
    const float* eb1 = (const float*)d_in[5];
    const float* eW2 = (const float*)d_in[6];
    const float* eb2 = (const float*)d_in[7];
    const float* eW3 = (const float*)d_in[8];
    const float* eb3 = (const float*)d_in[9];
    const float* nW1 = (const float*)d_in[10];
    const float* nb1 = (const float*)d_in[11];
    const float* nW2 = (const float*)d_in[12];
    const float* nb2 = (const float*)d_in[13];
    const float* nW3 = (const float*)d_in[14];
    const float* nb3 = (const float*)d_in[15];

    float* out_nf = (float*)d_out;
    float* out_ef = out_nf + (size_t)N_NODES * 32;

    cudaFuncSetAttribute(edge_kernel, cudaFuncAttributeMaxDynamicSharedMemorySize, EDGE_SMEM);
    cudaFuncSetAttribute(node_kernel, cudaFuncAttributeMaxDynamicSharedMemorySize, NODE_SMEM);

    prep_weights<<<44, 128>>>(eW1, eW2, eW3, nW1, nW2, nW3);
    zero_agg_kernel<<<3125, 256>>>();
    edge_kernel<<<N_EDGES / (128 * EDGE_TILES), 256, EDGE_SMEM>>>(
        nf, ef, src, dst, eb1, eb2, eb3, out_ef);
    node_kernel<<<(N_NODES + 255) / 256, 256, NODE_SMEM>>>(
        nf, nb1, nb2, nb3, out_nf);
}

// round 5
// speedup vs baseline: 3.8638x; 1.0919x over previous
#include <cuda_runtime.h>
#include <cuda_bf16.h>
#include <cstdint>
#include <cstddef>

#define N_NODES 100000
#define N_EDGES 1600000
#define EDGE_TILES 10   // 128-edge tiles per CTA -> 1250 CTAs (128 threads each)
#define NODE_TILES 2    // 128-node tiles per CTA -> 391 CTAs (256 threads)

// ---------------------------------------------------------------------------
// Device scratch
// ---------------------------------------------------------------------------
__device__ float g_agg[(size_t)N_NODES * 32];
// Fragment-order weight images: per (mat, kt, j, lane) a uint4 {bh0,bh1,bl0,bl1}
// eW1: uint4[   0..1535]  (6 kt x 8 j x 32 lanes)
// eW2: uint4[1536..2559]  (4 x 8 x 32)
// eW3: uint4[2560..3071]  (4 x 4 x 32)
// nW1: uint4[3072..4095], nW2: [4096..5119], nW3: [5120..5631]
__device__ __align__(16) uint4 g_wfrag[5632];

// ---------------------------------------------------------------------------
// Helpers
// ---------------------------------------------------------------------------
__device__ __forceinline__ uint32_t split2(float x0, float x1, uint32_t& lo) {
    uint32_t hw;
    asm("cvt.rn.bf16x2.f32 %0, %1, %2;" : "=r"(hw) : "f"(x1), "f"(x0));
    float h0 = __uint_as_float(hw << 16);
    float h1 = __uint_as_float(hw & 0xffff0000u);
    asm("cvt.rn.bf16x2.f32 %0, %1, %2;" : "=r"(lo) : "f"(x1 - h1), "f"(x0 - h0));
    return hw;
}

__device__ __forceinline__ void mma16816(float c[4], const uint32_t a[4],
                                         uint32_t b0, uint32_t b1) {
    asm("mma.sync.aligned.m16n8k16.row.col.f32.bf16.bf16.f32 "
        "{%0,%1,%2,%3},{%4,%5,%6,%7},{%8,%9},{%0,%1,%2,%3};"
        : "+f"(c[0]), "+f"(c[1]), "+f"(c[2]), "+f"(c[3])
        : "r"(a[0]), "r"(a[1]), "r"(a[2]), "r"(a[3]), "r"(b0), "r"(b1));
}

// dual-tile split-3 mma: one B-fragment load feeds 6 HMMA (tiles A and B)
__device__ __forceinline__ void mma3x2(float ca[4], float cb[4],
                                       const uint32_t ahA[4], const uint32_t alA[4],
                                       const uint32_t ahB[4], const uint32_t alB[4],
                                       const uint4* f) {
    uint4 b = *f;
    mma16816(ca, ahA, b.x, b.y);
    mma16816(cb, ahB, b.x, b.y);
    mma16816(ca, ahA, b.z, b.w);
    mma16816(cb, ahB, b.z, b.w);
    mma16816(ca, alA, b.x, b.y);
    mma16816(cb, alB, b.x, b.y);
}

// single-tile variant (node kernel)
__device__ __forceinline__ void mma3f(float c[4], const uint32_t ah[4], const uint32_t al[4],
                                      const uint4* f) {
    uint4 b = *f;
    mma16816(c, ah, b.x, b.y);
    mma16816(c, ah, b.z, b.w);
    mma16816(c, al, b.x, b.y);
}

__device__ __forceinline__ void red4(float* p, float4 v) {
    asm volatile("red.global.add.v4.f32 [%0], {%1,%2,%3,%4};"
                 :: "l"(p), "f"(v.x), "f"(v.y), "f"(v.z), "f"(v.w) : "memory");
}

// bias + relu + split c[8][4] (N=64) -> next-layer A fragments (4 k-tiles)
__device__ __forceinline__ void convert(const float c[8][4], const float* bias, int cc,
                                        uint32_t ah[4][4], uint32_t al[4][4]) {
    #pragma unroll
    for (int kk = 0; kk < 4; kk++) {
        #pragma unroll
        for (int h = 0; h < 2; h++) {
            int j = 2 * kk + h;
            float2 bb = *(const float2*)(bias + 8 * j + 2 * cc);
            float x0 = fmaxf(c[j][0] + bb.x, 0.f);
            float x1 = fmaxf(c[j][1] + bb.y, 0.f);
            float x2 = fmaxf(c[j][2] + bb.x, 0.f);
            float x3 = fmaxf(c[j][3] + bb.y, 0.f);
            ah[kk][2 * h]     = split2(x0, x1, al[kk][2 * h]);
            ah[kk][2 * h + 1] = split2(x2, x3, al[kk][2 * h + 1]);
        }
    }
}

// ---------------------------------------------------------------------------
// Prep: fragment-order hi/lo bf16 weight images. One uint4 per thread.
// ---------------------------------------------------------------------------
__global__ void prep_weights(const float* __restrict__ eW1, const float* __restrict__ eW2,
                             const float* __restrict__ eW3, const float* __restrict__ nW1,
                             const float* __restrict__ nW2, const float* __restrict__ nW3) {
    int id = blockIdx.x * blockDim.x + threadIdx.x;
    if (id >= 5632) return;
    const float* W; int NJ, N; int rel;
    if      (id < 1536) { W = eW1; NJ = 8; N = 64; rel = id; }
    else if (id < 2560) { W = eW2; NJ = 8; N = 64; rel = id - 1536; }
    else if (id < 3072) { W = eW3; NJ = 4; N = 32; rel = id - 2560; }
    else if (id < 4096) { W = nW1; NJ = 8; N = 64; rel = id - 3072; }
    else if (id < 5120) { W = nW2; NJ = 8; N = 64; rel = id - 4096; }
    else                { W = nW3; NJ = 4; N = 32; rel = id - 5120; }
    int lane = rel & 31, fi = rel >> 5;
    int kt = fi / NJ, j = fi % NJ;
    int n = 8 * j + (lane >> 2);
    int k0 = kt * 16 + 2 * (lane & 3);
    float x0 = W[(size_t)k0 * N + n];
    float x1 = W[(size_t)(k0 + 1) * N + n];
    float x2 = W[(size_t)(k0 + 8) * N + n];
    float x3 = W[(size_t)(k0 + 9) * N + n];
    uint4 o;
    o.x = split2(x0, x1, o.z);
    o.y = split2(x2, x3, o.w);
    g_wfrag[id] = o;
}

__global__ void zero_agg_kernel() {
    int i = blockIdx.x * blockDim.x + threadIdx.x;
    reinterpret_cast<float4*>(g_agg)[i] = make_float4(0.f, 0.f, 0.f, 0.f);
}

// ---------------------------------------------------------------------------
// Edge kernel: 128 threads = 4 warps, each warp = 32 edges/tile (two m16
// A-tiles sharing every B-fragment load), EDGE_TILES tiles per CTA.
// SMEM: 3072 uint4 weight frags (49152 B) + 160 bias + 4 warp bufs.
// ---------------------------------------------------------------------------
#define EDGE_WU4  3072
#define EDGE_SMEM (49152 + 640 + 4 * 2304)

__global__ void __launch_bounds__(128, 3)
edge_kernel(const float* __restrict__ nf, const float* __restrict__ ef,
            const int* __restrict__ src, const int* __restrict__ dst,
            const float* __restrict__ b1, const float* __restrict__ b2,
            const float* __restrict__ b3, float* __restrict__ out_ef) {
    extern __shared__ char sm[];
    const int tid = threadIdx.x, wid = tid >> 5, lane = tid & 31;

    uint4* wf = (uint4*)sm;
    for (int i = tid; i < EDGE_WU4; i += 128) wf[i] = g_wfrag[i];
    float* bias = (float*)(sm + 49152);
    if (tid < 64)       bias[tid] = b1[tid];
    else if (tid < 128) bias[tid] = b2[tid - 64];
    if (tid < 32)       bias[128 + tid] = b3[tid];
    float* buf = (float*)(sm + 49792) + wid * 576;
    __syncthreads();

    const int r = lane >> 2, cc = lane & 3;
    const uint4* F1 = wf;            // 6 kt x 8 j x 32
    const uint4* F2 = wf + 1536;     // 4 x 8 x 32
    const uint4* F3 = wf + 2560;     // 4 x 4 x 32

    for (int t = 0; t < EDGE_TILES; t++) {
        const int ew = (blockIdx.x * EDGE_TILES + t) * 128 + wid * 32;
        const int eA0 = ew + r,       eA1 = ew + 8 + r;
        const int eB0 = ew + 16 + r,  eB1 = ew + 24 + r;
        const int sA0 = src[eA0], sA1 = src[eA1], sB0 = src[eB0], sB1 = src[eB1];
        const int dA0 = dst[eA0], dA1 = dst[eA1], dB0 = dst[eB0], dB1 = dst[eB1];

        float cA[8][4], cB[8][4];
        #pragma unroll
        for (int j = 0; j < 8; j++)
            #pragma unroll
            for (int q = 0; q < 4; q++) { cA[j][q] = 0.f; cB[j][q] = 0.f; }

        // ---- L1: K = 96, A fragments gathered straight from global ----
        #pragma unroll
        for (int kt = 0; kt < 6; kt++) {
            const int cls = kt >> 1;
            const float *pA0, *pA1, *pB0, *pB1;
            if (cls == 0) {
                pA0 = nf + (size_t)sA0 * 32; pA1 = nf + (size_t)sA1 * 32;
                pB0 = nf + (size_t)sB0 * 32; pB1 = nf + (size_t)sB1 * 32;
            } else if (cls == 1) {
                pA0 = nf + (size_t)dA0 * 32; pA1 = nf + (size_t)dA1 * 32;
                pB0 = nf + (size_t)dB0 * 32; pB1 = nf + (size_t)dB1 * 32;
            } else {
                pA0 = ef + (size_t)eA0 * 32; pA1 = ef + (size_t)eA1 * 32;
                pB0 = ef + (size_t)eB0 * 32; pB1 = ef + (size_t)eB1 * 32;
            }
            const int o = ((kt & 1) << 4) + 2 * cc;
            float2 a00 = *(const float2*)(pA0 + o), a01 = *(const float2*)(pA0 + o + 8);
            float2 a10 = *(const float2*)(pA1 + o), a11 = *(const float2*)(pA1 + o + 8);
            float2 b00 = *(const float2*)(pB0 + o), b01 = *(const float2*)(pB0 + o + 8);
            float2 b10 = *(const float2*)(pB1 + o), b11 = *(const float2*)(pB1 + o + 8);
            uint32_t ahA[4], alA[4], ahB[4], alB[4];
            ahA[0] = split2(a00.x, a00.y, alA[0]);
            ahA[1] = split2(a10.x, a10.y, alA[1]);
            ahA[2] = split2(a01.x, a01.y, alA[2]);
            ahA[3] = split2(a11.x, a11.y, alA[3]);
            ahB[0] = split2(b00.x, b00.y, alB[0]);
            ahB[1] = split2(b10.x, b10.y, alB[1]);
            ahB[2] = split2(b01.x, b01.y, alB[2]);
            ahB[3] = split2(b11.x, b11.y, alB[3]);
            const uint4* fp = F1 + kt * 256 + lane;
            #pragma unroll
            for (int j = 0; j < 8; j++)
                mma3x2(cA[j], cB[j], ahA, alA, ahB, alB, fp + j * 32);
        }

        uint32_t a2hA[4][4], a2lA[4][4], a2hB[4][4], a2lB[4][4];
        convert(cA, bias, cc, a2hA, a2lA);
        convert(cB, bias, cc, a2hB, a2lB);

        // ---- L2: K = 64 ----
        #pragma unroll
        for (int j = 0; j < 8; j++)
            #pragma unroll
            for (int q = 0; q < 4; q++) { cA[j][q] = 0.f; cB[j][q] = 0.f; }
        #pragma unroll
        for (int kt = 0; kt < 4; kt++) {
            const uint4* fp = F2 + kt * 256 + lane;
            #pragma unroll
            for (int j = 0; j < 8; j++)
                mma3x2(cA[j], cB[j], a2hA[kt], a2lA[kt], a2hB[kt], a2lB[kt], fp + j * 32);
        }

        convert(cA, bias + 64, cc, a2hA, a2lA);   // reuse as a3
        convert(cB, bias + 64, cc, a2hB, a2lB);

        // ---- L3: K = 64, N = 32 (reuse cA/cB rows 0..3) ----
        #pragma unroll
        for (int j = 0; j < 4; j++)
            #pragma unroll
            for (int q = 0; q < 4; q++) { cA[j][q] = 0.f; cB[j][q] = 0.f; }
        #pragma unroll
        for (int kt = 0; kt < 4; kt++) {
            const uint4* fp = F3 + kt * 128 + lane;
            #pragma unroll
            for (int j = 0; j < 4; j++)
                mma3x2(cA[j], cB[j], a2hA[kt], a2lA[kt], a2hB[kt], a2lB[kt], fp + j * 32);
        }

        // ---- epilogue, half A then half B through the 16-row warp buf ----
        #pragma unroll
        for (int half = 0; half < 2; half++) {
            #pragma unroll
            for (int j = 0; j < 4; j++) {
                float2 bb = *(const float2*)(bias + 128 + 8 * j + 2 * cc);
                int col = 8 * j + 2 * cc;
                const float* cj = half ? cB[j] : cA[j];
                buf[r * 36 + col]           = fmaxf(cj[0] + bb.x, 0.f);
                buf[r * 36 + col + 1]       = fmaxf(cj[1] + bb.y, 0.f);
                buf[(r + 8) * 36 + col]     = fmaxf(cj[2] + bb.x, 0.f);
                buf[(r + 8) * 36 + col + 1] = fmaxf(cj[3] + bb.y, 0.f);
            }
            __syncwarp();
            {
                const int row = lane >> 1, hh = lane & 1;
                const int e_row = ew + half * 16 + row;
                const int d = dst[e_row];
                const float* bp = buf + row * 36 + hh * 16;
                float4 v0 = *(const float4*)(bp);
                float4 v1 = *(const float4*)(bp + 4);
                float4 v2 = *(const float4*)(bp + 8);
                float4 v3 = *(const float4*)(bp + 12);
                float4* op = (float4*)(out_ef + (size_t)e_row * 32 + hh * 16);
                op[0] = v0; op[1] = v1; op[2] = v2; op[3] = v3;
                float* ap = g_agg + (size_t)d * 32 + hh * 16;
                red4(ap, v0); red4(ap + 4, v1); red4(ap + 8, v2); red4(ap + 12, v3);
            }
            __syncwarp();
        }
    }
}

// ---------------------------------------------------------------------------
// Node kernel: 256 threads, NODE_TILES x 128 nodes per CTA (as R4).
// ---------------------------------------------------------------------------
#define NODE_WU4  2560
#define NODE_SMEM (40960 + 640 + 8 * 2304)

__global__ void __launch_bounds__(256, 2)
node_kernel(const float* __restrict__ nf,
            const float* __restrict__ b1, const float* __restrict__ b2,
            const float* __restrict__ b3, float* __restrict__ out_nf) {
    extern __shared__ char sm[];
    const int tid = threadIdx.x, wid = tid >> 5, lane = tid & 31;

    uint4* wf = (uint4*)sm;
    for (int i = tid; i < NODE_WU4; i += 256) wf[i] = g_wfrag[3072 + i];
    float* bias = (float*)(sm + 40960);
    if (tid < 64)       bias[tid] = b1[tid];
    else if (tid < 128) bias[tid] = b2[tid - 64];
    else if (tid < 160) bias[tid] = b3[tid - 128];
    float* buf = (float*)(sm + 41600) + wid * 576;
    __syncthreads();

    const int r = lane >> 2, cc = lane & 3;
    const uint4* F1 = wf;
    const uint4* F2 = wf + 1024;
    const uint4* F3 = wf + 2048;

    for (int t = 0; t < NODE_TILES; t++) {
        const int n0w = (blockIdx.x * NODE_TILES + t) * 128 + wid * 16;
        if (n0w >= N_NODES) break;
        const int ra = min(n0w + r, N_NODES - 1);
        const int rb = min(n0w + r + 8, N_NODES - 1);
        const float* PA[2] = { nf + (size_t)ra * 32, g_agg + (size_t)ra * 32 };
        const float* PB[2] = { nf + (size_t)rb * 32, g_agg + (size_t)rb * 32 };

        float c[8][4];
        #pragma unroll
        for (int j = 0; j < 8; j++) { c[j][0] = c[j][1] = c[j][2] = c[j][3] = 0.f; }

        #pragma unroll
        for (int kt = 0; kt < 4; kt++) {
            const float* pa = PA[kt >> 1];
            const float* pb = PB[kt >> 1];
            const int o = ((kt & 1) << 4) + 2 * cc;
            float2 va0 = *(const float2*)(pa + o), va1 = *(const float2*)(pa + o + 8);
            float2 vb0 = *(const float2*)(pb + o), vb1 = *(const float2*)(pb + o + 8);
            uint32_t ah[4], al[4];
            ah[0] = split2(va0.x, va0.y, al[0]);
            ah[1] = split2(vb0.x, vb0.y, al[1]);
            ah[2] = split2(va1.x, va1.y, al[2]);
            ah[3] = split2(vb1.x, vb1.y, al[3]);
            const uint4* fp = F1 + kt * 256 + lane;
            #pragma unroll
            for (int j = 0; j < 8; j++)
                mma3f(c[j], ah, al, fp + j * 32);
        }

        uint32_t a2h[4][4], a2l[4][4];
        convert(c, bias, cc, a2h, a2l);

        #pragma unroll
        for (int j = 0; j < 8; j++) { c[j][0] = c[j][1] = c[j][2] = c[j][3] = 0.f; }
        #pragma unroll
        for (int kt = 0; kt < 4; kt++) {
            const uint4* fp = F2 + kt * 256 + lane;
            #pragma unroll
            for (int j = 0; j < 8; j++)
                mma3f(c[j], a2h[kt], a2l[kt], fp + j * 32);
        }

        convert(c, bias + 64, cc, a2h, a2l);   // reuse as a3

        float c3[4][4];
        #pragma unroll
        for (int j = 0; j < 4; j++) { c3[j][0] = c3[j][1] = c3[j][2] = c3[j][3] = 0.f; }
        #pragma unroll
        for (int kt = 0; kt < 4; kt++) {
            const uint4* fp = F3 + kt * 128 + lane;
            #pragma unroll
            for (int j = 0; j < 4; j++)
                mma3f(c3[j], a2h[kt], a2l[kt], fp + j * 32);
        }

        #pragma unroll
        for (int j = 0; j < 4; j++) {
            float2 bb = *(const float2*)(bias + 128 + 8 * j + 2 * cc);
            int col = 8 * j + 2 * cc;
            buf[r * 36 + col]           = fmaxf(c3[j][0] + bb.x, 0.f);
            buf[r * 36 + col + 1]       = fmaxf(c3[j][1] + bb.y, 0.f);
            buf[(r + 8) * 36 + col]     = fmaxf(c3[j][2] + bb.x, 0.f);
            buf[(r + 8) * 36 + col + 1] = fmaxf(c3[j][3] + bb.y, 0.f);
        }
        __syncwarp();
        {
            const int row = lane >> 1, half = lane & 1;
            const int n_row = n0w + row;
            if (n_row < N_NODES) {
                const float* bp = buf + row * 36 + half * 16;
                float4* op = (float4*)(out_nf + (size_t)n_row * 32 + half * 16);
                op[0] = *(const float4*)(bp);
                op[1] = *(const float4*)(bp + 4);
                op[2] = *(const float4*)(bp + 8);
                op[3] = *(const float4*)(bp + 12);
            }
        }
        __syncwarp();
    }
}

// ---------------------------------------------------------------------------
extern "C" void kernel_launch(void* const* d_in, const int* in_sizes, int n_in,
                              void* d_out, int out_size) {
    const float* nf  = (const float*)d_in[0];
    const float* ef  = (const float*)d_in[1];
    const int*   src = (const int*)d_in[2];
    const int*   dst = (const int*)d_in[3];
    const float* eW1 = (const float*)d_in[4];
    const float* eb1 = (const float*)d_in[5];
    const float* eW2 = (const float*)d_in[6];
    const float* eb2 = (const float*)d_in[7];
    const float* eW3 = (const float*)d_in[8];
    const float* eb3 = (const float*)d_in[9];
    const float* nW1 = (const float*)d_in[10];
    const float* nb1 = (const float*)d_in[11];
    const float* nW2 = (const float*)d_in[12];
    const float* nb2 = (const float*)d_in[13];
    const float* nW3 = (const float*)d_in[14];
    const float* nb3 = (const float*)d_in[15];

    float* out_nf = (float*)d_out;
    float* out_ef = out_nf + (size_t)N_NODES * 32;

    cudaFuncSetAttribute(edge_kernel, cudaFuncAttributeMaxDynamicSharedMemorySize, EDGE_SMEM);
    cudaFuncSetAttribute(node_kernel, cudaFuncAttributeMaxDynamicSharedMemorySize, NODE_SMEM);

    prep_weights<<<44, 128>>>(eW1, eW2, eW3, nW1, nW2, nW3);
    zero_agg_kernel<<<3125, 256>>>();
    edge_kernel<<<N_EDGES / (128 * EDGE_TILES), 128, EDGE_SMEM>>>(
        nf, ef, src, dst, eb1, eb2, eb3, out_ef);
    node_kernel<<<(N_NODES + 255) / 256, 256, NODE_SMEM>>>(
        nf, nb1, nb2, nb3, out_nf);
}